// round 3
// baseline (speedup 1.0000x reference)
#include <cuda_runtime.h>

#define B_   8
#define C_   8
#define H_   512
#define W_   1024
#define HW_  (H_*W_)
#define NPIX (B_*HW_)
#define NQ   (HW_/4)

#define GX   64                  // x-blocks per image
#define NBLK (GX * B_)           // 512 blocks, single wave

// ---------------- device scratch (no allocations allowed) ----------------
// packed per-quad: bits[0..3] boundary flags, bits[4..15] 4x 3-bit target ids
__device__ unsigned short g_pk[B_ * NQ];              // 2 MiB
// per-block partial sums (written unconditionally -> no zeroing, no atomics)
// loss rows: 0..63 probsum(b*8+c), 64..127 inter(b*8+c), 128..135 ce(b), 136..143 cb(b)
__device__ float g_lp[144 * GX];
// boundary rows: 0..63 cnt(b*8+c)
__device__ float g_bp[64 * GX];
__device__ unsigned int g_ctr = 0;

// ---------------- helpers ----------------
__device__ __forceinline__ float wredf(float v) {
    #pragma unroll
    for (int o = 16; o; o >>= 1) v += __shfl_xor_sync(0xffffffffu, v, o);
    return v;
}
__device__ __forceinline__ int wredi(int v) {
    #pragma unroll
    for (int o = 16; o; o >>= 1) v += __shfl_xor_sync(0xffffffffu, v, o);
    return v;
}

// sliding 5-wide min/max over r[2+j .. 6+j] for j = 0..3 (shared pairwise stage)
__device__ __forceinline__ void win5(const int r[12], int wmn[4], int wmx[4]) {
    int pmn[7], pmx[7];
    #pragma unroll
    for (int i = 0; i < 7; i++) {
        pmn[i] = min(r[2+i], r[3+i]);
        pmx[i] = max(r[2+i], r[3+i]);
    }
    #pragma unroll
    for (int j = 0; j < 4; j++) {
        wmn[j] = min(min(pmn[j], pmn[j+2]), r[6+j]);
        wmx[j] = max(max(pmx[j], pmx[j+2]), r[6+j]);
    }
}

#define UNPACK4(dst, off, v) { dst[(off)+0]=(v).x; dst[(off)+1]=(v).y; dst[(off)+2]=(v).z; dst[(off)+3]=(v).w; }

// ---------------- kernel A: boundary flags + target pack + class counts ----------------
__global__ __launch_bounds__(256)
void boundary_kernel(const int* __restrict__ tgt) {
    const int b = blockIdx.y;
    const int* tgtb = tgt + (size_t)b * HW_;

    unsigned long long hist = 0ull;   // 8 byte-packed class counters (<=32 px/thread)

    const int stride = blockDim.x * GX;   // 16384 -> 8 iters
    #pragma unroll 1
    for (int q = blockIdx.x * blockDim.x + threadIdx.x; q < NQ; q += stride) {
        const int p0 = q << 2;
        const int h  = p0 >> 10;
        const int w0 = p0 & (W_ - 1);

        const int hm1 = h - 1, hp1 = h + 1, hm2 = h - 2, hp2 = h + 2;
        const bool ym1 = hm1 >= 0, yp1 = hp1 < H_;
        const bool ym2 = hm2 >= 0, yp2 = hp2 < H_;
        const int* row0  = tgtb + h * W_;
        const int* rowm1 = tgtb + (ym1 ? hm1 : 0)      * W_;
        const int* rowp1 = tgtb + (yp1 ? hp1 : (H_-1)) * W_;
        const int* rowm2 = tgtb + (ym2 ? hm2 : 0)      * W_;
        const int* rowp2 = tgtb + (yp2 ? hp2 : (H_-1)) * W_;

        const bool xin = (w0 >= 4) && (w0 <= W_ - 8);
        const int wl = xin ? w0 - 4 : w0;
        const int wr = xin ? w0 + 4 : w0;

        int r0a[12], rm1a[12], rp1a[12];
        {
            int4 v;
            v = *(const int4*)(row0  + wl); UNPACK4(r0a,  0, v);
            v = *(const int4*)(row0  + w0); UNPACK4(r0a,  4, v);
            v = *(const int4*)(row0  + wr); UNPACK4(r0a,  8, v);
            v = *(const int4*)(rowm1 + wl); UNPACK4(rm1a, 0, v);
            v = *(const int4*)(rowm1 + w0); UNPACK4(rm1a, 4, v);
            v = *(const int4*)(rowm1 + wr); UNPACK4(rm1a, 8, v);
            v = *(const int4*)(rowp1 + wl); UNPACK4(rp1a, 0, v);
            v = *(const int4*)(rowp1 + w0); UNPACK4(rp1a, 4, v);
            v = *(const int4*)(rowp1 + wr); UNPACK4(rp1a, 8, v);
        }
        int rm2a[4], rp2a[4];
        {
            int4 v;
            v = *(const int4*)(rowm2 + w0); UNPACK4(rm2a, 0, v);
            v = *(const int4*)(rowp2 + w0); UNPACK4(rp2a, 0, v);
        }

        int tv[4];
        #pragma unroll
        for (int j = 0; j < 4; j++) tv[j] = r0a[4 + j];

        int mn[4], mx[4];
        if (xin) {
            int a0n[4], a0x[4], amn[4], amx[4], apn[4], apx[4];
            win5(r0a,  a0n, a0x);
            win5(rm1a, amn, amx);
            win5(rp1a, apn, apx);
            #pragma unroll
            for (int j = 0; j < 4; j++) { mn[j] = a0n[j]; mx[j] = a0x[j]; }
            if (ym1) {
                #pragma unroll
                for (int j = 0; j < 4; j++) { mn[j] = min(mn[j], amn[j]); mx[j] = max(mx[j], amx[j]); }
            }
            if (yp1) {
                #pragma unroll
                for (int j = 0; j < 4; j++) { mn[j] = min(mn[j], apn[j]); mx[j] = max(mx[j], apx[j]); }
            }
        } else {
            #pragma unroll
            for (int j = 0; j < 4; j++) {
                const int cen = tv[j];
                int a = cen, z = cen;
                #pragma unroll
                for (int dx = -2; dx <= 2; dx++) {
                    const int xx = w0 + j + dx;
                    const bool vx = ((unsigned)xx < (unsigned)W_);
                    const int idx = 4 + j + dx;
                    int v0 = vx ? r0a[idx] : cen;
                    int v1 = (vx && ym1) ? rm1a[idx] : cen;
                    int v2 = (vx && yp1) ? rp1a[idx] : cen;
                    a = min(a, min(v0, min(v1, v2)));
                    z = max(z, max(v0, max(v1, v2)));
                }
                mn[j] = a; mx[j] = z;
            }
        }
        if (ym2) {
            #pragma unroll
            for (int j = 0; j < 4; j++) { mn[j] = min(mn[j], rm2a[j]); mx[j] = max(mx[j], rm2a[j]); }
        }
        if (yp2) {
            #pragma unroll
            for (int j = 0; j < 4; j++) { mn[j] = min(mn[j], rp2a[j]); mx[j] = max(mx[j], rp2a[j]); }
        }

        unsigned pk = 0;
        #pragma unroll
        for (int j = 0; j < 4; j++) {
            pk |= (mx[j] > mn[j]) ? (1u << j) : 0u;
            pk |= ((unsigned)tv[j]) << (4 + 3 * j);
            hist += 1ull << (tv[j] << 3);
        }
        g_pk[(size_t)b * NQ + q] = (unsigned short)pk;
    }

    // unpack histogram -> warp reduce -> block reduce -> per-block slot write
    int cnt[8];
    #pragma unroll
    for (int c = 0; c < 8; c++) cnt[c] = (int)((hist >> (c * 8)) & 0xffull);
    #pragma unroll
    for (int c = 0; c < 8; c++) cnt[c] = wredi(cnt[c]);

    __shared__ int scnt[8][8];
    const int wid = threadIdx.x >> 5, lane = threadIdx.x & 31;
    if (lane == 0) {
        #pragma unroll
        for (int c = 0; c < 8; c++) scnt[wid][c] = cnt[c];
    }
    __syncthreads();
    if (threadIdx.x < 8) {
        int s = 0;
        #pragma unroll
        for (int w = 0; w < 8; w++) s += scnt[w][threadIdx.x];
        // row = b*8+c, col = blockIdx.x
        g_bp[(b * 8 + threadIdx.x) * GX + blockIdx.x] = (float)s;
    }
}

// ---------------- kernel B: softmax / CE / dice partials + last-block finalize ----------------
__global__ __launch_bounds__(256)
void loss_kernel(const float* __restrict__ pred, float* __restrict__ out) {
    const int b = blockIdx.y;
    const float* predb = pred + (size_t)b * (C_ * HW_);
    const unsigned short* pkb = g_pk + (size_t)b * NQ;

    float probsum[8], inter[8];
    #pragma unroll
    for (int c = 0; c < 8; c++) { probsum[c] = 0.f; inter[c] = 0.f; }
    float ce_s = 0.f, cb_s = 0.f;

    const int stride = blockDim.x * GX;   // 16384 -> 8 iters
    #pragma unroll 1
    for (int q = blockIdx.x * blockDim.x + threadIdx.x; q < NQ; q += stride) {
        const int p0 = q << 2;
        const unsigned pk = pkb[q];

        float4 pv[8];
        #pragma unroll
        for (int c = 0; c < 8; c++)
            pv[c] = *(const float4*)(predb + (size_t)c * HW_ + p0);

        #pragma unroll
        for (int j = 0; j < 4; j++) {
            float v[8];
            #pragma unroll
            for (int c = 0; c < 8; c++) {
                const float4 f = pv[c];
                v[c] = (j == 0) ? f.x : (j == 1) ? f.y : (j == 2) ? f.z : f.w;
            }

            // pred ~ N(0,1): exp without max-subtraction is numerically safe
            float e[8]; float s = 0.f;
            #pragma unroll
            for (int c = 0; c < 8; c++) { e[c] = __expf(v[c]); s += e[c]; }

            const float inv = __fdividef(1.f, s);
            const int t = (pk >> (4 + 3 * j)) & 7;

            float et = e[0];
            #pragma unroll
            for (int c = 0; c < 8; c++) {
                const bool mm = (t == c);
                const float pc = e[c] * inv;
                probsum[c] += pc;
                inter[c]   += mm ? pc : 0.f;
                if (c > 0) et = mm ? e[c] : et;
            }

            const float lp = __logf(et * inv);   // log p_t
            ce_s -= lp;
            if ((pk >> j) & 1u) cb_s -= lp;
        }
    }

    // warp reduce 18 values -> smem -> block reduce -> per-block slot write
    #pragma unroll
    for (int c = 0; c < 8; c++) { probsum[c] = wredf(probsum[c]); inter[c] = wredf(inter[c]); }
    ce_s = wredf(ce_s);
    cb_s = wredf(cb_s);

    __shared__ float sred[8][18];
    const int wid = threadIdx.x >> 5, lane = threadIdx.x & 31;
    if (lane == 0) {
        #pragma unroll
        for (int c = 0; c < 8; c++) { sred[wid][c] = probsum[c]; sred[wid][8 + c] = inter[c]; }
        sred[wid][16] = ce_s; sred[wid][17] = cb_s;
    }
    __syncthreads();
    if (threadIdx.x < 18) {
        float s = 0.f;
        #pragma unroll
        for (int w = 0; w < 8; w++) s += sred[w][threadIdx.x];
        const int i = threadIdx.x;
        int row;
        if      (i < 8)  row = b * 8 + i;          // probsum
        else if (i < 16) row = 64 + b * 8 + (i-8); // inter
        else if (i == 16) row = 128 + b;           // ce
        else              row = 136 + b;           // cb
        g_lp[row * GX + blockIdx.x] = s;
    }

    // ---- last block finalizes ----
    __shared__ unsigned int s_ticket;
    __threadfence();
    __syncthreads();
    if (threadIdx.x == 0) s_ticket = atomicAdd(&g_ctr, 1u);
    __syncthreads();
    if (s_ticket != NBLK - 1) return;

    // sum the per-block slots: 144 loss rows + 64 cnt rows, 64 cols each
    __shared__ float S[208];
    const int t = threadIdx.x;
    if (t < 208) {
        const float* rowp = (t < 144) ? &g_lp[t * GX] : &g_bp[(t - 144) * GX];
        float s = 0.f;
        #pragma unroll
        for (int x = 0; x < GX; x++) s += rowp[x];
        S[t] = s;
    }
    __syncthreads();

    __shared__ float dpart[2];
    if (t < 64) {
        float term = (2.f * S[64 + t] + 1e-6f) / (S[t] + S[144 + t] + 1e-6f);
        term = wredf(term);
        if ((t & 31) == 0) dpart[t >> 5] = term;
    }
    __syncthreads();
    if (t == 0) {
        float ce = 0.f, cb = 0.f;
        #pragma unroll
        for (int k = 0; k < 8; k++) { ce += S[128 + k]; cb += S[136 + k]; }
        const float invN = 1.f / (float)NPIX;
        const float ce_m = ce * invN;
        const float bd   = (ce + 9.f * cb) * invN;       // wmap: 10 on boundary, 1 else
        const float dice = 1.f - (dpart[0] + dpart[1]) * (1.f / 64.f);
        out[0] = 1.f * ce_m + 3.f * dice + 2.f * bd;
        g_ctr = 0;   // reset for next graph replay (deterministic)
    }
}

// ---------------- launch ----------------
extern "C" void kernel_launch(void* const* d_in, const int* in_sizes, int n_in,
                              void* d_out, int out_size) {
    (void)n_in; (void)out_size;
    const float* pred;
    const int*   tgt;
    if (in_sizes[0] == B_ * C_ * HW_) {
        pred = (const float*)d_in[0];
        tgt  = (const int*)d_in[1];
    } else {
        pred = (const float*)d_in[1];
        tgt  = (const int*)d_in[0];
    }
    boundary_kernel<<<dim3(GX, B_), 256>>>(tgt);
    loss_kernel<<<dim3(GX, B_), 256>>>(pred, (float*)d_out);
}

// round 4
// speedup vs baseline: 1.1176x; 1.1176x over previous
#include <cuda_runtime.h>

#define B_   8
#define C_   8
#define H_   512
#define W_   1024
#define HW_  (H_*W_)
#define NPIX (B_*HW_)
#define NQ   (HW_/4)

#define GX    128                 // x-blocks per image
#define NBLK  (GX * B_)           // 1024 blocks
#define ITERS (NQ / (256 * GX))   // 4 quads per thread, exact

// ---------------- device scratch (no allocations allowed) ----------------
// per-block partial sums, written unconditionally (no zeroing, no atomics)
// rows: 0..63 probsum(b*8+c), 64..127 inter(b*8+c), 128..135 ce(b),
//       136..143 cb(b), 144..207 cnt(b*8+c)
__device__ float g_lp[208 * GX];
__device__ unsigned int g_ctr = 0;

// ---------------- helpers ----------------
__device__ __forceinline__ float wredf(float v) {
    #pragma unroll
    for (int o = 16; o; o >>= 1) v += __shfl_xor_sync(0xffffffffu, v, o);
    return v;
}

// sliding 5-wide min/max over r[2+j .. 6+j] for j = 0..3 (shared pairwise stage)
__device__ __forceinline__ void win5(const int r[12], int wmn[4], int wmx[4]) {
    int pmn[7], pmx[7];
    #pragma unroll
    for (int i = 0; i < 7; i++) {
        pmn[i] = min(r[2+i], r[3+i]);
        pmx[i] = max(r[2+i], r[3+i]);
    }
    #pragma unroll
    for (int j = 0; j < 4; j++) {
        wmn[j] = min(min(pmn[j], pmn[j+2]), r[6+j]);
        wmx[j] = max(max(pmx[j], pmx[j+2]), r[6+j]);
    }
}

#define UNPACK4(dst, off, v) { dst[(off)+0]=(v).x; dst[(off)+1]=(v).y; dst[(off)+2]=(v).z; dst[(off)+3]=(v).w; }

// ---------------- single fused kernel ----------------
__global__ __launch_bounds__(256, 4)
void fused_kernel(const float* __restrict__ pred, const int* __restrict__ tgt,
                  float* __restrict__ out) {
    const int b = blockIdx.y;
    const float* predb = pred + (size_t)b * (C_ * HW_);
    const int*   tgtb  = tgt  + (size_t)b * HW_;

    const int q0     = blockIdx.x * blockDim.x + threadIdx.x;
    const int stride = blockDim.x * GX;   // 32768

    // ============ phase 1: morphology boundary + class histogram ============
    unsigned bflags = 0;                  // 4 bits per iteration
    unsigned long long hist = 0ull;       // 8 byte-packed class counters (<=16/class)

    #pragma unroll 1
    for (int it = 0; it < ITERS; it++) {
        const int q  = q0 + it * stride;
        const int p0 = q << 2;
        const int h  = p0 >> 10;
        const int w0 = p0 & (W_ - 1);

        const int hm1 = h - 1, hp1 = h + 1, hm2 = h - 2, hp2 = h + 2;
        const bool ym1 = hm1 >= 0, yp1 = hp1 < H_;
        const bool ym2 = hm2 >= 0, yp2 = hp2 < H_;
        const int* row0  = tgtb + h * W_;
        const int* rowm1 = tgtb + (ym1 ? hm1 : 0)      * W_;
        const int* rowp1 = tgtb + (yp1 ? hp1 : (H_-1)) * W_;
        const int* rowm2 = tgtb + (ym2 ? hm2 : 0)      * W_;
        const int* rowp2 = tgtb + (yp2 ? hp2 : (H_-1)) * W_;

        const bool xin = (w0 >= 4) && (w0 <= W_ - 8);
        const int wl = xin ? w0 - 4 : w0;
        const int wr = xin ? w0 + 4 : w0;

        int r0a[12], rm1a[12], rp1a[12];
        {
            int4 v;
            v = *(const int4*)(row0  + wl); UNPACK4(r0a,  0, v);
            v = *(const int4*)(row0  + w0); UNPACK4(r0a,  4, v);
            v = *(const int4*)(row0  + wr); UNPACK4(r0a,  8, v);
            v = *(const int4*)(rowm1 + wl); UNPACK4(rm1a, 0, v);
            v = *(const int4*)(rowm1 + w0); UNPACK4(rm1a, 4, v);
            v = *(const int4*)(rowm1 + wr); UNPACK4(rm1a, 8, v);
            v = *(const int4*)(rowp1 + wl); UNPACK4(rp1a, 0, v);
            v = *(const int4*)(rowp1 + w0); UNPACK4(rp1a, 4, v);
            v = *(const int4*)(rowp1 + wr); UNPACK4(rp1a, 8, v);
        }
        int rm2a[4], rp2a[4];
        {
            int4 v;
            v = *(const int4*)(rowm2 + w0); UNPACK4(rm2a, 0, v);
            v = *(const int4*)(rowp2 + w0); UNPACK4(rp2a, 0, v);
        }

        int tv[4];
        #pragma unroll
        for (int j = 0; j < 4; j++) tv[j] = r0a[4 + j];

        int mn[4], mx[4];
        if (xin) {
            int a0n[4], a0x[4], amn[4], amx[4], apn[4], apx[4];
            win5(r0a,  a0n, a0x);
            win5(rm1a, amn, amx);
            win5(rp1a, apn, apx);
            #pragma unroll
            for (int j = 0; j < 4; j++) { mn[j] = a0n[j]; mx[j] = a0x[j]; }
            if (ym1) {
                #pragma unroll
                for (int j = 0; j < 4; j++) { mn[j] = min(mn[j], amn[j]); mx[j] = max(mx[j], amx[j]); }
            }
            if (yp1) {
                #pragma unroll
                for (int j = 0; j < 4; j++) { mn[j] = min(mn[j], apn[j]); mx[j] = max(mx[j], apx[j]); }
            }
        } else {
            #pragma unroll
            for (int j = 0; j < 4; j++) {
                const int cen = tv[j];
                int a = cen, z = cen;
                #pragma unroll
                for (int dx = -2; dx <= 2; dx++) {
                    const int xx = w0 + j + dx;
                    const bool vx = ((unsigned)xx < (unsigned)W_);
                    const int idx = 4 + j + dx;
                    int v0 = vx ? r0a[idx] : cen;
                    int v1 = (vx && ym1) ? rm1a[idx] : cen;
                    int v2 = (vx && yp1) ? rp1a[idx] : cen;
                    a = min(a, min(v0, min(v1, v2)));
                    z = max(z, max(v0, max(v1, v2)));
                }
                mn[j] = a; mx[j] = z;
            }
        }
        if (ym2) {
            #pragma unroll
            for (int j = 0; j < 4; j++) { mn[j] = min(mn[j], rm2a[j]); mx[j] = max(mx[j], rm2a[j]); }
        }
        if (yp2) {
            #pragma unroll
            for (int j = 0; j < 4; j++) { mn[j] = min(mn[j], rp2a[j]); mx[j] = max(mx[j], rp2a[j]); }
        }

        unsigned bits = 0;
        #pragma unroll
        for (int j = 0; j < 4; j++) {
            bits |= (mx[j] > mn[j]) ? (1u << j) : 0u;
            hist += 1ull << (tv[j] << 3);
        }
        bflags |= bits << (4 * it);
    }

    // ============ phase 2: softmax / CE / dice (tgt re-read hits L2) ============
    float probsum[8], inter[8];
    #pragma unroll
    for (int c = 0; c < 8; c++) { probsum[c] = 0.f; inter[c] = 0.f; }
    float ce_s = 0.f, cb_s = 0.f;

    #pragma unroll 1
    for (int it = 0; it < ITERS; it++) {
        const int q  = q0 + it * stride;
        const int p0 = q << 2;
        const int4 tq = *(const int4*)(tgtb + p0);
        const int tv[4] = { tq.x, tq.y, tq.z, tq.w };
        const unsigned bits = (bflags >> (4 * it)) & 0xFu;

        float4 pv[8];
        #pragma unroll
        for (int c = 0; c < 8; c++)
            pv[c] = *(const float4*)(predb + (size_t)c * HW_ + p0);

        #pragma unroll
        for (int j = 0; j < 4; j++) {
            // pred ~ N(0,1): exp without max-subtraction is numerically safe
            float e[8]; float s = 0.f;
            #pragma unroll
            for (int c = 0; c < 8; c++) {
                const float4 f = pv[c];
                const float v = (j == 0) ? f.x : (j == 1) ? f.y : (j == 2) ? f.z : f.w;
                e[c] = __expf(v); s += e[c];
            }

            const float inv = __fdividef(1.f, s);
            const int t = tv[j];

            float et = e[0];
            #pragma unroll
            for (int c = 0; c < 8; c++) {
                const bool mm = (t == c);
                const float pc = e[c] * inv;
                probsum[c] += pc;
                inter[c]   += mm ? pc : 0.f;
                if (c > 0) et = mm ? e[c] : et;
            }

            const float lp = __logf(et * inv);   // log p_t
            ce_s -= lp;
            if ((bits >> j) & 1u) cb_s -= lp;
        }
    }

    // ============ block reduction -> per-block slots ============
    #pragma unroll
    for (int c = 0; c < 8; c++) { probsum[c] = wredf(probsum[c]); inter[c] = wredf(inter[c]); }
    ce_s = wredf(ce_s);
    cb_s = wredf(cb_s);
    float cntf[8];
    #pragma unroll
    for (int c = 0; c < 8; c++) cntf[c] = wredf((float)(int)((hist >> (c * 8)) & 0xffull));

    __shared__ float sred[8][26];
    const int wid = threadIdx.x >> 5, lane = threadIdx.x & 31;
    if (lane == 0) {
        #pragma unroll
        for (int c = 0; c < 8; c++) {
            sred[wid][c]      = probsum[c];
            sred[wid][8 + c]  = inter[c];
            sred[wid][18 + c] = cntf[c];
        }
        sred[wid][16] = ce_s; sred[wid][17] = cb_s;
    }
    __syncthreads();
    if (threadIdx.x < 26) {
        float s = 0.f;
        #pragma unroll
        for (int w = 0; w < 8; w++) s += sred[w][threadIdx.x];
        const int i = threadIdx.x;
        int row;
        if      (i < 8)   row = b * 8 + i;            // probsum
        else if (i < 16)  row = 64 + b * 8 + (i - 8); // inter
        else if (i == 16) row = 128 + b;              // ce
        else if (i == 17) row = 136 + b;              // cb
        else              row = 144 + b * 8 + (i-18); // cnt
        g_lp[row * GX + blockIdx.x] = s;
    }

    // ============ last block finalizes ============
    __shared__ unsigned int s_ticket;
    __threadfence();
    __syncthreads();
    if (threadIdx.x == 0) s_ticket = atomicAdd(&g_ctr, 1u);
    __syncthreads();
    if (s_ticket != NBLK - 1) return;

    __shared__ float S[208];
    const int t = threadIdx.x;
    if (t < 208) {
        const float* rowp = &g_lp[t * GX];
        float s = 0.f;
        #pragma unroll 8
        for (int x = 0; x < GX; x++) s += rowp[x];
        S[t] = s;
    }
    __syncthreads();

    __shared__ float dpart[2];
    if (t < 64) {
        float term = (2.f * S[64 + t] + 1e-6f) / (S[t] + S[144 + t] + 1e-6f);
        term = wredf(term);
        if ((t & 31) == 0) dpart[t >> 5] = term;
    }
    __syncthreads();
    if (t == 0) {
        float ce = 0.f, cb = 0.f;
        #pragma unroll
        for (int k = 0; k < 8; k++) { ce += S[128 + k]; cb += S[136 + k]; }
        const float invN = 1.f / (float)NPIX;
        const float ce_m = ce * invN;
        const float bd   = (ce + 9.f * cb) * invN;       // wmap: 10 on boundary, 1 else
        const float dice = 1.f - (dpart[0] + dpart[1]) * (1.f / 64.f);
        out[0] = 1.f * ce_m + 3.f * dice + 2.f * bd;
        g_ctr = 0;   // reset for next graph replay (deterministic)
    }
}

// ---------------- launch ----------------
extern "C" void kernel_launch(void* const* d_in, const int* in_sizes, int n_in,
                              void* d_out, int out_size) {
    (void)n_in; (void)out_size;
    const float* pred;
    const int*   tgt;
    if (in_sizes[0] == B_ * C_ * HW_) {
        pred = (const float*)d_in[0];
        tgt  = (const int*)d_in[1];
    } else {
        pred = (const float*)d_in[1];
        tgt  = (const int*)d_in[0];
    }
    fused_kernel<<<dim3(GX, B_), 256>>>(pred, tgt, (float*)d_out);
}